// round 16
// baseline (speedup 1.0000x reference)
#include <cuda_runtime.h>
#include <cuda_fp16.h>
#include <cstdint>
#include <math.h>

#define NB 4
#define NW 2048
#define DM 1024
#define NH 16
#define DK 64
#define MT (NB*NW)
#define MWPR (NW/32)

// ---------------- device scratch ----------------
__device__ unsigned g_mb[NB*NW*MWPR];
__device__ __half g_x16[(size_t)3*MT*DM];   // Q,K,V inputs fp16
__device__ __half g_ao[(size_t)MT*DM];      // attention output fp16
__device__ __half g_w16[(size_t)4*DM*DM];   // Wq,Wk,Wv,Wo fp16
__device__ __half g_q16[NB*NH*NW*DK];       // q (scale folded)
__device__ __half g_k16[NB*NH*NW*DK];
__device__ __half g_v16[NB*NH*NW*DK];

// ---------------- PTX helpers ----------------
__device__ __forceinline__ uint32_t smem_u32(const void* p) {
    uint32_t a;
    asm("{ .reg .u64 t; cvta.to.shared.u64 t, %1; cvt.u32.u64 %0, t; }" : "=r"(a) : "l"(p));
    return a;
}
#define CP_ASYNC16(sa, g) \
    asm volatile("cp.async.cg.shared.global [%0], [%1], 16;" :: "r"(sa), "l"(g))
#define CP_COMMIT() asm volatile("cp.async.commit_group;" ::: "memory")
#define CP_WAIT1()  asm volatile("cp.async.wait_group 1;" ::: "memory")
#define CP_WAIT0()  asm volatile("cp.async.wait_group 0;" ::: "memory")

#define LDSM4(r, addr) \
    asm volatile("ldmatrix.sync.aligned.m8n8.x4.shared.b16 {%0,%1,%2,%3}, [%4];" \
        : "=r"((r)[0]), "=r"((r)[1]), "=r"((r)[2]), "=r"((r)[3]) : "r"(addr))
#define LDSM4T(r, addr) \
    asm volatile("ldmatrix.sync.aligned.m8n8.x4.trans.shared.b16 {%0,%1,%2,%3}, [%4];" \
        : "=r"((r)[0]), "=r"((r)[1]), "=r"((r)[2]), "=r"((r)[3]) : "r"(addr))

#define MMAF16(d, a, b0, b1) \
    asm volatile("mma.sync.aligned.m16n8k16.row.col.f32.f16.f16.f32 " \
        "{%0,%1,%2,%3}, {%4,%5,%6,%7}, {%8,%9}, {%0,%1,%2,%3};" \
        : "+f"((d)[0]), "+f"((d)[1]), "+f"((d)[2]), "+f"((d)[3]) \
        : "r"((a)[0]), "r"((a)[1]), "r"((a)[2]), "r"((a)[3]), "r"(b0), "r"(b1))

#define PACK_F16X2(r, lo, hi) \
    asm("cvt.rn.f16x2.f32 %0, %1, %2;" : "=r"(r) : "f"(hi), "f"(lo))

// ---- GEMM smem geometry: CTA 128x128, 8 warps (4x2), warp 32x64, 2 stages ----
// tiles: X, W — each 128 rows x 32 halves, row stride 40
#define BKC    32
#define RS     40
#define X_OFF  0
#define W_OFF  5120
#define STAGE_EL 10240
#define SMEM_MMA (2*STAGE_EL*2)         // 40960 B -> 2 CTAs/SM

// ---- flash smem geometry (K, V single) ----
#define FRS    72
#define FTS    (64*FRS)
#define FSTAGE (2*FTS)
#define SMEM_FLASH (2*FSTAGE*2)          // 36864 B

#define NX_ELEMS  ((size_t)MT*DM)
#define NWT_ELEMS ((size_t)DM*DM)
#define PACK_BLKS  ((NB*NW*NW)/1024)     // 16384
#define CONVX_BLKS ((3*MT*DM)/1024)      // 24576
#define CONVW_BLKS ((4*DM*DM)/1024)      // 4096
#define PREP_BLKS  (PACK_BLKS + CONVX_BLKS + CONVW_BLKS)

// ============================================================
// prep: mask pack (int4 vectorized) + fp32->fp16 conversions
// ============================================================
__global__ void __launch_bounds__(256) prep_kernel(
    const int* __restrict__ mask,
    const float* __restrict__ Q, const float* __restrict__ K, const float* __restrict__ V,
    const float* __restrict__ Wq, const float* __restrict__ Wk,
    const float* __restrict__ Wv, const float* __restrict__ Wo)
{
    __shared__ uint8_t nib[256];
    int bid = blockIdx.x, tid = threadIdx.x;
    if (bid < PACK_BLKS) {
        const int4* mp = (const int4*)mask;
        int4 v = mp[(size_t)bid * 256 + tid];
        unsigned n = (unsigned)(v.x != 0) | ((unsigned)(v.y != 0) << 1)
                   | ((unsigned)(v.z != 0) << 2) | ((unsigned)(v.w != 0) << 3);
        nib[tid] = (uint8_t)n;
        __syncthreads();
        if (tid < 32) {
            const uint8_t* p = nib + tid * 8;
            unsigned w = 0;
            #pragma unroll
            for (int i = 0; i < 8; i++) w |= ((unsigned)p[i]) << (4 * i);
            g_mb[bid * 32 + tid] = w;
        }
        return;
    }
    bid -= PACK_BLKS;
    if (bid < CONVX_BLKS) {
        size_t i = ((size_t)bid * 256 + tid) * 4;
        const float* src; size_t off;
        if (i < NX_ELEMS)            { src = Q; off = i; }
        else if (i < 2 * NX_ELEMS)   { src = K; off = i - NX_ELEMS; }
        else                         { src = V; off = i - 2 * NX_ELEMS; }
        float4 v = *(const float4*)(src + off);
        ((__half2*)(g_x16 + i))[0] = __floats2half2_rn(v.x, v.y);
        ((__half2*)(g_x16 + i))[1] = __floats2half2_rn(v.z, v.w);
        return;
    }
    bid -= CONVX_BLKS;
    {
        size_t i = ((size_t)bid * 256 + tid) * 4;
        const float* src; size_t off;
        if (i < NWT_ELEMS)            { src = Wq; off = i; }
        else if (i < 2 * NWT_ELEMS)   { src = Wk; off = i - NWT_ELEMS; }
        else if (i < 3 * NWT_ELEMS)   { src = Wv; off = i - 2 * NWT_ELEMS; }
        else                          { src = Wo; off = i - 3 * NWT_ELEMS; }
        float4 v = *(const float4*)(src + off);
        ((__half2*)(g_w16 + i))[0] = __floats2half2_rn(v.x, v.y);
        ((__half2*)(g_w16 + i))[1] = __floats2half2_rn(v.z, v.w);
    }
}

// ============================================================
// GEMM: C[128x128] = X[m0:+128,:] * W[n0:+128,:]^T, pure fp16 1-term
// 256 threads, 8 warps (4x2), warp tile 32x64
// ============================================================
__device__ __forceinline__ void issue_stage(
    const __half* __restrict__ x, const __half* __restrict__ w,
    int m0, int n0, int kt, uint32_t stage_sb, int tid)
{
    #pragma unroll
    for (int t = 0; t < 4; t++) {
        int tile = t >> 1;                   // 0=X 1=W
        int rem = tid + (t & 1) * 256;       // 0..511
        int row = rem >> 2, cq = rem & 3;
        const __half* base = (tile == 0) ? x : w;
        int rb = (tile == 0) ? m0 : n0;
        size_t g = (size_t)(rb + row) * DM + kt * BKC + cq * 8;
        uint32_t sa = stage_sb + (uint32_t)(tile * 5120 + row * RS + cq * 8) * 2;
        CP_ASYNC16(sa, base + g);
    }
}

__device__ __forceinline__ void mma_mainloop(
    const __half* __restrict__ x, const __half* __restrict__ w,
    int m0, int n0, __half* sbuf, float acc[2][8][4])
{
    int tid = threadIdx.x;
    int wid = tid >> 5, lane = tid & 31;
    int wm = wid >> 1, wn = wid & 1;
    int lr = lane & 15, lc = lane >> 4;

    uint32_t sb = smem_u32(sbuf);
    uint32_t stage_sb[2] = { sb, sb + (uint32_t)STAGE_EL * 2 };

    issue_stage(x, w, m0, n0, 0, stage_sb[0], tid);
    CP_COMMIT();

    for (int kt = 0; kt < DM / BKC; kt++) {
        int s = kt & 1;
        if (kt < DM / BKC - 1) {
            issue_stage(x, w, m0, n0, kt + 1, stage_sb[s ^ 1], tid);
            CP_COMMIT();
            CP_WAIT1();
        } else {
            CP_WAIT0();
        }
        __syncthreads();

        uint32_t ab = stage_sb[s];
        #pragma unroll
        for (int kk = 0; kk < BKC; kk += 16) {
            uint32_t af[2][4];
            #pragma unroll
            for (int mi = 0; mi < 2; mi++) {
                uint32_t off = (uint32_t)((wm * 32 + mi * 16 + lr) * RS + kk + lc * 8) * 2;
                LDSM4(af[mi], ab + X_OFF * 2 + off);
            }
            #pragma unroll
            for (int ni = 0; ni < 4; ni++) {
                uint32_t bf[4];
                uint32_t off = (uint32_t)((wn * 64 + ni * 16 + lr) * RS + kk + lc * 8) * 2;
                LDSM4(bf, ab + W_OFF * 2 + off);
                #pragma unroll
                for (int mi = 0; mi < 2; mi++)
                    #pragma unroll
                    for (int hf = 0; hf < 2; hf++)
                        MMAF16(acc[mi][ni * 2 + hf], af[mi], bf[hf], bf[hf + 2]);
            }
        }
        __syncthreads();
    }
}

// ============================================================
// Projection GEMM: writes fp16 head-major q/k/v
// ============================================================
__global__ void __launch_bounds__(256, 2) proj_mma_kernel() {
    extern __shared__ __half sbuf[];
    int z = blockIdx.z;
    int m0 = blockIdx.y * 128, n0 = blockIdx.x * 128;
    const __half* x = g_x16 + (size_t)z * MT * DM;
    const __half* w = g_w16 + (size_t)z * DM * DM;
    __half* dst = (z == 0) ? g_q16 : (z == 1) ? g_k16 : g_v16;
    float scale = (z == 0) ? 0.125f : 1.0f;

    float acc[2][8][4];
    #pragma unroll
    for (int i = 0; i < 2; i++)
        #pragma unroll
        for (int j = 0; j < 8; j++)
            acc[i][j][0] = acc[i][j][1] = acc[i][j][2] = acc[i][j][3] = 0.f;

    mma_mainloop(x, w, m0, n0, sbuf, acc);

    int tid = threadIdx.x, wid = tid >> 5, lane = tid & 31;
    int wm = wid >> 1, wn = wid & 1;
    int h = (n0 + wn * 64) >> 6;
    #pragma unroll
    for (int mi = 0; mi < 2; mi++)
        #pragma unroll
        for (int nj = 0; nj < 8; nj++) {
            int d = nj * 8 + (lane & 3) * 2;
            int m = m0 + wm * 32 + mi * 16 + (lane >> 2);
            int bb = m >> 11, t = m & (NW - 1);
            size_t off0 = ((size_t)(bb * NH + h) * NW + t) * DK + d;
            *(__half2*)(dst + off0) =
                __floats2half2_rn(acc[mi][nj][0] * scale, acc[mi][nj][1] * scale);
            *(__half2*)(dst + off0 + 8 * DK) =
                __floats2half2_rn(acc[mi][nj][2] * scale, acc[mi][nj][3] * scale);
        }
}

// ============================================================
// Output GEMM: attn(fp16) @ Wo^T(fp16) -> fp32
// ============================================================
__global__ void __launch_bounds__(256, 2) out_mma_kernel(float* __restrict__ out) {
    extern __shared__ __half sbuf[];
    int m0 = blockIdx.y * 128, n0 = blockIdx.x * 128;
    const __half* w = g_w16 + (size_t)3 * DM * DM;

    float acc[2][8][4];
    #pragma unroll
    for (int i = 0; i < 2; i++)
        #pragma unroll
        for (int j = 0; j < 8; j++)
            acc[i][j][0] = acc[i][j][1] = acc[i][j][2] = acc[i][j][3] = 0.f;

    mma_mainloop(g_ao, w, m0, n0, sbuf, acc);

    int tid = threadIdx.x, wid = tid >> 5, lane = tid & 31;
    int wm = wid >> 1, wn = wid & 1;
    #pragma unroll
    for (int mi = 0; mi < 2; mi++)
        #pragma unroll
        for (int nj = 0; nj < 8; nj++) {
            int n = n0 + wn * 64 + nj * 8 + (lane & 3) * 2;
            int m = m0 + wm * 32 + mi * 16 + (lane >> 2);
            *(float2*)(out + (size_t)m * DM + n) = make_float2(acc[mi][nj][0], acc[mi][nj][1]);
            *(float2*)(out + (size_t)(m + 8) * DM + n) = make_float2(acc[mi][nj][2], acc[mi][nj][3]);
        }
}

// ============================================================
// Flash attention: pure fp16; 256 threads, 8 warps, 16 q/warp, 2 CTAs/SM
// ============================================================
__device__ __forceinline__ void flash_issue(
    int kt, uint32_t stage_sb, int tid, size_t hb)
{
    const __half* gb[2] = { g_k16 + hb, g_v16 + hb };
    #pragma unroll
    for (int t = 0; t < 4; t++) {
        int tile = t >> 1;
        int rem = tid + (t & 1) * 256;
        int row = rem >> 3, cq = rem & 7;
        const __half* g = gb[tile] + (size_t)(kt * 64 + row) * DK + cq * 8;
        uint32_t sa = stage_sb + (uint32_t)(tile * FTS + row * FRS + cq * 8) * 2;
        CP_ASYNC16(sa, g);
    }
}

__global__ void __launch_bounds__(256, 2) flash_mma_kernel() {
    extern __shared__ __half fsm[];
    int b = blockIdx.z, h = blockIdx.y, q0 = blockIdx.x * 128;
    int tid = threadIdx.x, wid = tid >> 5, lane = tid & 31;
    int lr = lane & 15, lc = lane >> 4;
    int gr = lane >> 2, c = lane & 3;

    size_t hb = (size_t)(b * NH + h) * NW * DK;
    const __half* qp = g_q16 + hb + (size_t)q0 * DK;

    uint32_t qf[4][4];
    #pragma unroll
    for (int kc = 0; kc < 4; kc++) {
        int r0 = wid * 16 + gr, col = kc * 16 + 2 * c;
        qf[kc][0] = *(const uint32_t*)(qp + (size_t)r0 * DK + col);
        qf[kc][1] = *(const uint32_t*)(qp + (size_t)(r0 + 8) * DK + col);
        qf[kc][2] = *(const uint32_t*)(qp + (size_t)r0 * DK + col + 8);
        qf[kc][3] = *(const uint32_t*)(qp + (size_t)(r0 + 8) * DK + col + 8);
    }

    float oacc[8][4];
    #pragma unroll
    for (int j = 0; j < 8; j++)
        oacc[j][0] = oacc[j][1] = oacc[j][2] = oacc[j][3] = 0.f;
    float m0 = -INFINITY, m1 = -INFINITY, l0 = 0.f, l1 = 0.f;

    uint32_t sb = smem_u32(fsm);
    flash_issue(0, sb, tid, hb);
    CP_COMMIT();

    for (int kt = 0; kt < NW / 64; kt++) {
        int s = kt & 1;
        uint32_t ss = sb + (uint32_t)(s * FSTAGE) * 2;
        if (kt < NW / 64 - 1) {
            flash_issue(kt + 1, sb + (uint32_t)((s ^ 1) * FSTAGE) * 2, tid, hb);
            CP_COMMIT();
            CP_WAIT1();
        } else {
            CP_WAIT0();
        }
        __syncthreads();

        const unsigned* mb0 = g_mb + (size_t)(b * NW + q0 + wid * 16 + gr) * MWPR + kt * 2;
        unsigned mw00 = mb0[0], mw01 = mb0[1];
        unsigned mw10 = mb0[8 * MWPR], mw11 = mb0[8 * MWPR + 1];

        float sacc[8][4];
        #pragma unroll
        for (int j = 0; j < 8; j++)
            sacc[j][0] = sacc[j][1] = sacc[j][2] = sacc[j][3] = 0.f;

        #pragma unroll
        for (int kc = 0; kc < 4; kc++) {
            #pragma unroll
            for (int g = 0; g < 4; g++) {
                uint32_t kf[4];
                uint32_t off = (uint32_t)((g * 16 + lr) * FRS + kc * 16 + lc * 8) * 2;
                LDSM4(kf, ss + off);
                #pragma unroll
                for (int hf = 0; hf < 2; hf++)
                    MMAF16(sacc[2 * g + hf], qf[kc], kf[hf], kf[hf + 2]);
            }
        }

        #pragma unroll
        for (int j = 0; j < 8; j++) {
            unsigned wr0 = (j < 4) ? mw00 : mw01;
            unsigned wr1 = (j < 4) ? mw10 : mw11;
            int bit = (8 * j + 2 * c) & 31;
            if (!((wr0 >> bit) & 1u))       sacc[j][0] = -1e9f;
            if (!((wr0 >> (bit + 1)) & 1u)) sacc[j][1] = -1e9f;
            if (!((wr1 >> bit) & 1u))       sacc[j][2] = -1e9f;
            if (!((wr1 >> (bit + 1)) & 1u)) sacc[j][3] = -1e9f;
        }

        float mx0 = -INFINITY, mx1 = -INFINITY;
        #pragma unroll
        for (int j = 0; j < 8; j++) {
            mx0 = fmaxf(mx0, fmaxf(sacc[j][0], sacc[j][1]));
            mx1 = fmaxf(mx1, fmaxf(sacc[j][2], sacc[j][3]));
        }
        mx0 = fmaxf(mx0, __shfl_xor_sync(0xffffffffu, mx0, 1));
        mx0 = fmaxf(mx0, __shfl_xor_sync(0xffffffffu, mx0, 2));
        mx1 = fmaxf(mx1, __shfl_xor_sync(0xffffffffu, mx1, 1));
        mx1 = fmaxf(mx1, __shfl_xor_sync(0xffffffffu, mx1, 2));

        float nm0 = fmaxf(m0, mx0), nm1 = fmaxf(m1, mx1);
        float sc0 = __expf(m0 - nm0), sc1 = __expf(m1 - nm1);
        float rs0 = 0.f, rs1 = 0.f;
        #pragma unroll
        for (int j = 0; j < 8; j++) {
            sacc[j][0] = __expf(sacc[j][0] - nm0);
            sacc[j][1] = __expf(sacc[j][1] - nm0);
            sacc[j][2] = __expf(sacc[j][2] - nm1);
            sacc[j][3] = __expf(sacc[j][3] - nm1);
            rs0 += sacc[j][0] + sacc[j][1];
            rs1 += sacc[j][2] + sacc[j][3];
        }
        rs0 += __shfl_xor_sync(0xffffffffu, rs0, 1);
        rs0 += __shfl_xor_sync(0xffffffffu, rs0, 2);
        rs1 += __shfl_xor_sync(0xffffffffu, rs1, 1);
        rs1 += __shfl_xor_sync(0xffffffffu, rs1, 2);
        m0 = nm0; m1 = nm1;
        l0 = l0 * sc0 + rs0;
        l1 = l1 * sc1 + rs1;
        #pragma unroll
        for (int j = 0; j < 8; j++) {
            oacc[j][0] *= sc0; oacc[j][1] *= sc0;
            oacc[j][2] *= sc1; oacc[j][3] *= sc1;
        }

        uint32_t pf[4][4];
        #pragma unroll
        for (int kc = 0; kc < 4; kc++) {
            #pragma unroll
            for (int q = 0; q < 4; q++) {
                int jt = 2 * kc + (q >> 1);
                float p0 = sacc[jt][(q & 1) ? 2 : 0];
                float p1 = sacc[jt][(q & 1) ? 3 : 1];
                uint32_t hp;
                PACK_F16X2(hp, p0, p1);
                pf[kc][q] = hp;
            }
        }

        #pragma unroll
        for (int kc = 0; kc < 4; kc++) {
            #pragma unroll
            for (int dg = 0; dg < 4; dg++) {
                uint32_t vf[4];
                uint32_t off = (uint32_t)((kc * 16 + lr) * FRS + dg * 16 + lc * 8) * 2;
                LDSM4T(vf, ss + (uint32_t)FTS * 2 + off);
                MMAF16(oacc[2 * dg],     pf[kc], vf[0], vf[1]);
                MMAF16(oacc[2 * dg + 1], pf[kc], vf[2], vf[3]);
            }
        }
        __syncthreads();
    }

    float inv0 = 1.f / l0, inv1 = 1.f / l1;
    int row0 = q0 + wid * 16 + gr;
    size_t base0 = ((size_t)b * NW + row0) * DM + h * DK;
    #pragma unroll
    for (int j = 0; j < 8; j++) {
        int d = 8 * j + 2 * c;
        *(__half2*)(g_ao + base0 + d) =
            __floats2half2_rn(oacc[j][0] * inv0, oacc[j][1] * inv0);
        *(__half2*)(g_ao + base0 + 8 * DM + d) =
            __floats2half2_rn(oacc[j][2] * inv1, oacc[j][3] * inv1);
    }
}

// ============================================================
extern "C" void kernel_launch(void* const* d_in, const int* in_sizes, int n_in,
                              void* d_out, int out_size) {
    const float* Q  = (const float*)d_in[0];
    const float* K  = (const float*)d_in[1];
    const float* V  = (const float*)d_in[2];
    const int* mask = (const int*)d_in[3];
    const float* Wq = (const float*)d_in[4];
    const float* Wk = (const float*)d_in[5];
    const float* Wv = (const float*)d_in[6];
    const float* Wo = (const float*)d_in[7];
    float* out = (float*)d_out;

    static int attr_done = 0;
    if (!attr_done) {
        cudaFuncSetAttribute(proj_mma_kernel, cudaFuncAttributeMaxDynamicSharedMemorySize, SMEM_MMA);
        cudaFuncSetAttribute(out_mma_kernel, cudaFuncAttributeMaxDynamicSharedMemorySize, SMEM_MMA);
        cudaFuncSetAttribute(flash_mma_kernel, cudaFuncAttributeMaxDynamicSharedMemorySize, SMEM_FLASH);
        attr_done = 1;
    }

    prep_kernel<<<PREP_BLKS, 256>>>(mask, Q, K, V, Wq, Wk, Wv, Wo);
    proj_mma_kernel<<<dim3(DM / 128, MT / 128, 3), 256, SMEM_MMA>>>();
    flash_mma_kernel<<<dim3(NW / 128, NH, NB), 256, SMEM_FLASH>>>();
    out_mma_kernel<<<dim3(DM / 128, MT / 128), 256, SMEM_MMA>>>(out);
}

// round 17
// speedup vs baseline: 1.0892x; 1.0892x over previous
#include <cuda_runtime.h>
#include <cuda_fp16.h>
#include <cstdint>
#include <math.h>

#define NB 4
#define NW 2048
#define DM 1024
#define NH 16
#define DK 64
#define MT (NB*NW)
#define MWPR (NW/32)

// ---------------- device scratch ----------------
__device__ unsigned g_mb[NB*NW*MWPR];
__device__ __half g_x16[(size_t)3*MT*DM];   // Q,K,V inputs fp16
__device__ __half g_ao[(size_t)MT*DM];      // attention output fp16
__device__ __half g_w16[(size_t)4*DM*DM];   // Wq,Wk,Wv,Wo fp16
__device__ __half g_q16[NB*NH*NW*DK];       // q (scale folded)
__device__ __half g_k16[NB*NH*NW*DK];
__device__ __half g_v16[NB*NH*NW*DK];

// ---------------- PTX helpers ----------------
__device__ __forceinline__ uint32_t smem_u32(const void* p) {
    uint32_t a;
    asm("{ .reg .u64 t; cvta.to.shared.u64 t, %1; cvt.u32.u64 %0, t; }" : "=r"(a) : "l"(p));
    return a;
}
#define CP_ASYNC16(sa, g) \
    asm volatile("cp.async.cg.shared.global [%0], [%1], 16;" :: "r"(sa), "l"(g))
#define CP_COMMIT() asm volatile("cp.async.commit_group;" ::: "memory")
#define CP_WAIT1()  asm volatile("cp.async.wait_group 1;" ::: "memory")
#define CP_WAIT0()  asm volatile("cp.async.wait_group 0;" ::: "memory")

#define LDSM4(r, addr) \
    asm volatile("ldmatrix.sync.aligned.m8n8.x4.shared.b16 {%0,%1,%2,%3}, [%4];" \
        : "=r"((r)[0]), "=r"((r)[1]), "=r"((r)[2]), "=r"((r)[3]) : "r"(addr))
#define LDSM4T(r, addr) \
    asm volatile("ldmatrix.sync.aligned.m8n8.x4.trans.shared.b16 {%0,%1,%2,%3}, [%4];" \
        : "=r"((r)[0]), "=r"((r)[1]), "=r"((r)[2]), "=r"((r)[3]) : "r"(addr))

#define MMAF16(d, a, b0, b1) \
    asm volatile("mma.sync.aligned.m16n8k16.row.col.f32.f16.f16.f32 " \
        "{%0,%1,%2,%3}, {%4,%5,%6,%7}, {%8,%9}, {%0,%1,%2,%3};" \
        : "+f"((d)[0]), "+f"((d)[1]), "+f"((d)[2]), "+f"((d)[3]) \
        : "r"((a)[0]), "r"((a)[1]), "r"((a)[2]), "r"((a)[3]), "r"(b0), "r"(b1))

#define PACK_F16X2(r, lo, hi) \
    asm("cvt.rn.f16x2.f32 %0, %1, %2;" : "=r"(r) : "f"(hi), "f"(lo))

// ---- GEMM smem geometry: CTA 128x128, 8 warps (4x2), warp 32x64, BKC=64, 2 stages ----
#define BKC    64
#define RS     72
#define TILE_EL (128*RS)                 // 9216
#define X_OFF  0
#define W_OFF  TILE_EL
#define STAGE_EL (2*TILE_EL)             // 18432
#define SMEM_MMA (2*STAGE_EL*2)          // 73728 B -> 2 CTAs/SM

// ---- flash smem geometry: K,V of 128 keys per stage ----
#define FRS    72
#define FT2    (128*FRS)                 // one 128-key tile (elements)
#define FSTAGE (2*FT2)                   // K + V
#define SMEM_FLASH (2*FSTAGE*2)          // 73728 B

#define NX_ELEMS  ((size_t)MT*DM)
#define NWT_ELEMS ((size_t)DM*DM)
#define PACK_BLKS  ((NB*NW*NW)/1024)     // 16384
#define CONVX_BLKS ((3*MT*DM)/1024)      // 24576
#define CONVW_BLKS ((4*DM*DM)/1024)      // 4096
#define PREP_BLKS  (PACK_BLKS + CONVX_BLKS + CONVW_BLKS)

// ============================================================
// prep: mask pack (int4 vectorized) + fp32->fp16 conversions
// ============================================================
__global__ void __launch_bounds__(256) prep_kernel(
    const int* __restrict__ mask,
    const float* __restrict__ Q, const float* __restrict__ K, const float* __restrict__ V,
    const float* __restrict__ Wq, const float* __restrict__ Wk,
    const float* __restrict__ Wv, const float* __restrict__ Wo)
{
    __shared__ uint8_t nib[256];
    int bid = blockIdx.x, tid = threadIdx.x;
    if (bid < PACK_BLKS) {
        const int4* mp = (const int4*)mask;
        int4 v = mp[(size_t)bid * 256 + tid];
        unsigned n = (unsigned)(v.x != 0) | ((unsigned)(v.y != 0) << 1)
                   | ((unsigned)(v.z != 0) << 2) | ((unsigned)(v.w != 0) << 3);
        nib[tid] = (uint8_t)n;
        __syncthreads();
        if (tid < 32) {
            const uint8_t* p = nib + tid * 8;
            unsigned w = 0;
            #pragma unroll
            for (int i = 0; i < 8; i++) w |= ((unsigned)p[i]) << (4 * i);
            g_mb[bid * 32 + tid] = w;
        }
        return;
    }
    bid -= PACK_BLKS;
    if (bid < CONVX_BLKS) {
        size_t i = ((size_t)bid * 256 + tid) * 4;
        const float* src; size_t off;
        if (i < NX_ELEMS)            { src = Q; off = i; }
        else if (i < 2 * NX_ELEMS)   { src = K; off = i - NX_ELEMS; }
        else                         { src = V; off = i - 2 * NX_ELEMS; }
        float4 v = *(const float4*)(src + off);
        ((__half2*)(g_x16 + i))[0] = __floats2half2_rn(v.x, v.y);
        ((__half2*)(g_x16 + i))[1] = __floats2half2_rn(v.z, v.w);
        return;
    }
    bid -= CONVX_BLKS;
    {
        size_t i = ((size_t)bid * 256 + tid) * 4;
        const float* src; size_t off;
        if (i < NWT_ELEMS)            { src = Wq; off = i; }
        else if (i < 2 * NWT_ELEMS)   { src = Wk; off = i - NWT_ELEMS; }
        else if (i < 3 * NWT_ELEMS)   { src = Wv; off = i - 2 * NWT_ELEMS; }
        else                          { src = Wo; off = i - 3 * NWT_ELEMS; }
        float4 v = *(const float4*)(src + off);
        ((__half2*)(g_w16 + i))[0] = __floats2half2_rn(v.x, v.y);
        ((__half2*)(g_w16 + i))[1] = __floats2half2_rn(v.z, v.w);
    }
}

// ============================================================
// GEMM: C[128x128] = X[m0:+128,:] * W[n0:+128,:]^T, fp16 1-term, BKC=64
// 256 threads, 8 warps (4x2), warp tile 32x64
// ============================================================
__device__ __forceinline__ void issue_stage(
    const __half* __restrict__ x, const __half* __restrict__ w,
    int m0, int n0, int kt, uint32_t stage_sb, int tid)
{
    #pragma unroll
    for (int t = 0; t < 8; t++) {
        int tile = t >> 2;                   // 0=X 1=W
        int rem = tid + (t & 3) * 256;       // 0..1023
        int row = rem >> 3, cq = rem & 7;
        const __half* base = (tile == 0) ? x : w;
        int rb = (tile == 0) ? m0 : n0;
        size_t g = (size_t)(rb + row) * DM + kt * BKC + cq * 8;
        uint32_t sa = stage_sb + (uint32_t)(tile * TILE_EL + row * RS + cq * 8) * 2;
        CP_ASYNC16(sa, base + g);
    }
}

__device__ __forceinline__ void mma_mainloop(
    const __half* __restrict__ x, const __half* __restrict__ w,
    int m0, int n0, __half* sbuf, float acc[2][8][4])
{
    int tid = threadIdx.x;
    int wid = tid >> 5, lane = tid & 31;
    int wm = wid >> 1, wn = wid & 1;
    int lr = lane & 15, lc = lane >> 4;

    uint32_t sb = smem_u32(sbuf);
    uint32_t stage_sb[2] = { sb, sb + (uint32_t)STAGE_EL * 2 };

    issue_stage(x, w, m0, n0, 0, stage_sb[0], tid);
    CP_COMMIT();

    for (int kt = 0; kt < DM / BKC; kt++) {
        int s = kt & 1;
        if (kt < DM / BKC - 1) {
            issue_stage(x, w, m0, n0, kt + 1, stage_sb[s ^ 1], tid);
            CP_COMMIT();
            CP_WAIT1();
        } else {
            CP_WAIT0();
        }
        __syncthreads();

        uint32_t ab = stage_sb[s];
        #pragma unroll
        for (int kk = 0; kk < BKC; kk += 16) {
            uint32_t af[2][4];
            #pragma unroll
            for (int mi = 0; mi < 2; mi++) {
                uint32_t off = (uint32_t)((wm * 32 + mi * 16 + lr) * RS + kk + lc * 8) * 2;
                LDSM4(af[mi], ab + X_OFF * 2 + off);
            }
            #pragma unroll
            for (int ni = 0; ni < 4; ni++) {
                uint32_t bf[4];
                uint32_t off = (uint32_t)((wn * 64 + ni * 16 + lr) * RS + kk + lc * 8) * 2;
                LDSM4(bf, ab + W_OFF * 2 + off);
                #pragma unroll
                for (int mi = 0; mi < 2; mi++)
                    #pragma unroll
                    for (int hf = 0; hf < 2; hf++)
                        MMAF16(acc[mi][ni * 2 + hf], af[mi], bf[hf], bf[hf + 2]);
            }
        }
        __syncthreads();
    }
}

// ============================================================
// Projection GEMM: writes fp16 head-major q/k/v
// ============================================================
__global__ void __launch_bounds__(256, 2) proj_mma_kernel() {
    extern __shared__ __half sbuf[];
    int z = blockIdx.z;
    int m0 = blockIdx.y * 128, n0 = blockIdx.x * 128;
    const __half* x = g_x16 + (size_t)z * MT * DM;
    const __half* w = g_w16 + (size_t)z * DM * DM;
    __half* dst = (z == 0) ? g_q16 : (z == 1) ? g_k16 : g_v16;
    float scale = (z == 0) ? 0.125f : 1.0f;

    float acc[2][8][4];
    #pragma unroll
    for (int i = 0; i < 2; i++)
        #pragma unroll
        for (int j = 0; j < 8; j++)
            acc[i][j][0] = acc[i][j][1] = acc[i][j][2] = acc[i][j][3] = 0.f;

    mma_mainloop(x, w, m0, n0, sbuf, acc);

    int tid = threadIdx.x, wid = tid >> 5, lane = tid & 31;
    int wm = wid >> 1, wn = wid & 1;
    int h = (n0 + wn * 64) >> 6;
    #pragma unroll
    for (int mi = 0; mi < 2; mi++)
        #pragma unroll
        for (int nj = 0; nj < 8; nj++) {
            int d = nj * 8 + (lane & 3) * 2;
            int m = m0 + wm * 32 + mi * 16 + (lane >> 2);
            int bb = m >> 11, t = m & (NW - 1);
            size_t off0 = ((size_t)(bb * NH + h) * NW + t) * DK + d;
            *(__half2*)(dst + off0) =
                __floats2half2_rn(acc[mi][nj][0] * scale, acc[mi][nj][1] * scale);
            *(__half2*)(dst + off0 + 8 * DK) =
                __floats2half2_rn(acc[mi][nj][2] * scale, acc[mi][nj][3] * scale);
        }
}

// ============================================================
// Output GEMM: attn(fp16) @ Wo^T(fp16) -> fp32
// ============================================================
__global__ void __launch_bounds__(256, 2) out_mma_kernel(float* __restrict__ out) {
    extern __shared__ __half sbuf[];
    int m0 = blockIdx.y * 128, n0 = blockIdx.x * 128;
    const __half* w = g_w16 + (size_t)3 * DM * DM;

    float acc[2][8][4];
    #pragma unroll
    for (int i = 0; i < 2; i++)
        #pragma unroll
        for (int j = 0; j < 8; j++)
            acc[i][j][0] = acc[i][j][1] = acc[i][j][2] = acc[i][j][3] = 0.f;

    mma_mainloop(g_ao, w, m0, n0, sbuf, acc);

    int tid = threadIdx.x, wid = tid >> 5, lane = tid & 31;
    int wm = wid >> 1, wn = wid & 1;
    #pragma unroll
    for (int mi = 0; mi < 2; mi++)
        #pragma unroll
        for (int nj = 0; nj < 8; nj++) {
            int n = n0 + wn * 64 + nj * 8 + (lane & 3) * 2;
            int m = m0 + wm * 32 + mi * 16 + (lane >> 2);
            *(float2*)(out + (size_t)m * DM + n) = make_float2(acc[mi][nj][0], acc[mi][nj][1]);
            *(float2*)(out + (size_t)(m + 8) * DM + n) = make_float2(acc[mi][nj][2], acc[mi][nj][3]);
        }
}

// ============================================================
// Flash attention: fp16; 128-key stages, two 64-key softmax passes per stage
// 256 threads, 8 warps, 16 q/warp, 2 CTAs/SM
// ============================================================
__device__ __forceinline__ void flash_issue(
    int kt, uint32_t stage_sb, int tid, size_t hb)
{
    const __half* gb[2] = { g_k16 + hb, g_v16 + hb };
    #pragma unroll
    for (int t = 0; t < 8; t++) {
        int tile = t >> 2;                   // 0=K 1=V
        int rem = tid + (t & 3) * 256;       // 0..1023
        int row = rem >> 3, cq = rem & 7;
        const __half* g = gb[tile] + (size_t)(kt * 128 + row) * DK + cq * 8;
        uint32_t sa = stage_sb + (uint32_t)(tile * FT2 + row * FRS + cq * 8) * 2;
        CP_ASYNC16(sa, g);
    }
}

__global__ void __launch_bounds__(256, 2) flash_mma_kernel() {
    extern __shared__ __half fsm[];
    int b = blockIdx.z, h = blockIdx.y, q0 = blockIdx.x * 128;
    int tid = threadIdx.x, wid = tid >> 5, lane = tid & 31;
    int lr = lane & 15, lc = lane >> 4;
    int gr = lane >> 2, c = lane & 3;

    size_t hb = (size_t)(b * NH + h) * NW * DK;
    const __half* qp = g_q16 + hb + (size_t)q0 * DK;

    uint32_t qf[4][4];
    #pragma unroll
    for (int kc = 0; kc < 4; kc++) {
        int r0 = wid * 16 + gr, col = kc * 16 + 2 * c;
        qf[kc][0] = *(const uint32_t*)(qp + (size_t)r0 * DK + col);
        qf[kc][1] = *(const uint32_t*)(qp + (size_t)(r0 + 8) * DK + col);
        qf[kc][2] = *(const uint32_t*)(qp + (size_t)r0 * DK + col + 8);
        qf[kc][3] = *(const uint32_t*)(qp + (size_t)(r0 + 8) * DK + col + 8);
    }

    float oacc[8][4];
    #pragma unroll
    for (int j = 0; j < 8; j++)
        oacc[j][0] = oacc[j][1] = oacc[j][2] = oacc[j][3] = 0.f;
    float m0 = -INFINITY, m1 = -INFINITY, l0 = 0.f, l1 = 0.f;

    uint32_t sb = smem_u32(fsm);
    flash_issue(0, sb, tid, hb);
    CP_COMMIT();

    const unsigned* mrow0 = g_mb + (size_t)(b * NW + q0 + wid * 16 + gr) * MWPR;

    for (int kt = 0; kt < NW / 128; kt++) {
        int s = kt & 1;
        uint32_t ss = sb + (uint32_t)(s * FSTAGE) * 2;
        if (kt < NW / 128 - 1) {
            flash_issue(kt + 1, sb + (uint32_t)((s ^ 1) * FSTAGE) * 2, tid, hb);
            CP_COMMIT();
            CP_WAIT1();
        } else {
            CP_WAIT0();
        }
        __syncthreads();

        #pragma unroll
        for (int half = 0; half < 2; half++) {
            uint32_t ks = ss + (uint32_t)(half * 64 * FRS) * 2;            // K rows
            uint32_t vs = ss + (uint32_t)(FT2 + half * 64 * FRS) * 2;      // V rows
            const unsigned* mb0 = mrow0 + (kt * 2 + half) * 2;
            unsigned mw00 = mb0[0], mw01 = mb0[1];
            unsigned mw10 = mb0[8 * MWPR], mw11 = mb0[8 * MWPR + 1];

            float sacc[8][4];
            #pragma unroll
            for (int j = 0; j < 8; j++)
                sacc[j][0] = sacc[j][1] = sacc[j][2] = sacc[j][3] = 0.f;

            #pragma unroll
            for (int kc = 0; kc < 4; kc++) {
                #pragma unroll
                for (int g = 0; g < 4; g++) {
                    uint32_t kf[4];
                    uint32_t off = (uint32_t)((g * 16 + lr) * FRS + kc * 16 + lc * 8) * 2;
                    LDSM4(kf, ks + off);
                    #pragma unroll
                    for (int hf = 0; hf < 2; hf++)
                        MMAF16(sacc[2 * g + hf], qf[kc], kf[hf], kf[hf + 2]);
                }
            }

            #pragma unroll
            for (int j = 0; j < 8; j++) {
                unsigned wr0 = (j < 4) ? mw00 : mw01;
                unsigned wr1 = (j < 4) ? mw10 : mw11;
                int bit = (8 * j + 2 * c) & 31;
                if (!((wr0 >> bit) & 1u))       sacc[j][0] = -1e9f;
                if (!((wr0 >> (bit + 1)) & 1u)) sacc[j][1] = -1e9f;
                if (!((wr1 >> bit) & 1u))       sacc[j][2] = -1e9f;
                if (!((wr1 >> (bit + 1)) & 1u)) sacc[j][3] = -1e9f;
            }

            float mx0 = -INFINITY, mx1 = -INFINITY;
            #pragma unroll
            for (int j = 0; j < 8; j++) {
                mx0 = fmaxf(mx0, fmaxf(sacc[j][0], sacc[j][1]));
                mx1 = fmaxf(mx1, fmaxf(sacc[j][2], sacc[j][3]));
            }
            mx0 = fmaxf(mx0, __shfl_xor_sync(0xffffffffu, mx0, 1));
            mx0 = fmaxf(mx0, __shfl_xor_sync(0xffffffffu, mx0, 2));
            mx1 = fmaxf(mx1, __shfl_xor_sync(0xffffffffu, mx1, 1));
            mx1 = fmaxf(mx1, __shfl_xor_sync(0xffffffffu, mx1, 2));

            float nm0 = fmaxf(m0, mx0), nm1 = fmaxf(m1, mx1);
            float sc0 = __expf(m0 - nm0), sc1 = __expf(m1 - nm1);
            float rs0 = 0.f, rs1 = 0.f;
            #pragma unroll
            for (int j = 0; j < 8; j++) {
                sacc[j][0] = __expf(sacc[j][0] - nm0);
                sacc[j][1] = __expf(sacc[j][1] - nm0);
                sacc[j][2] = __expf(sacc[j][2] - nm1);
                sacc[j][3] = __expf(sacc[j][3] - nm1);
                rs0 += sacc[j][0] + sacc[j][1];
                rs1 += sacc[j][2] + sacc[j][3];
            }
            rs0 += __shfl_xor_sync(0xffffffffu, rs0, 1);
            rs0 += __shfl_xor_sync(0xffffffffu, rs0, 2);
            rs1 += __shfl_xor_sync(0xffffffffu, rs1, 1);
            rs1 += __shfl_xor_sync(0xffffffffu, rs1, 2);
            m0 = nm0; m1 = nm1;
            l0 = l0 * sc0 + rs0;
            l1 = l1 * sc1 + rs1;
            #pragma unroll
            for (int j = 0; j < 8; j++) {
                oacc[j][0] *= sc0; oacc[j][1] *= sc0;
                oacc[j][2] *= sc1; oacc[j][3] *= sc1;
            }

            uint32_t pf[4][4];
            #pragma unroll
            for (int kc = 0; kc < 4; kc++) {
                #pragma unroll
                for (int q = 0; q < 4; q++) {
                    int jt = 2 * kc + (q >> 1);
                    float p0 = sacc[jt][(q & 1) ? 2 : 0];
                    float p1 = sacc[jt][(q & 1) ? 3 : 1];
                    uint32_t hp;
                    PACK_F16X2(hp, p0, p1);
                    pf[kc][q] = hp;
                }
            }

            #pragma unroll
            for (int kc = 0; kc < 4; kc++) {
                #pragma unroll
                for (int dg = 0; dg < 4; dg++) {
                    uint32_t vf[4];
                    uint32_t off = (uint32_t)((kc * 16 + lr) * FRS + dg * 16 + lc * 8) * 2;
                    LDSM4T(vf, vs + off);
                    MMAF16(oacc[2 * dg],     pf[kc], vf[0], vf[1]);
                    MMAF16(oacc[2 * dg + 1], pf[kc], vf[2], vf[3]);
                }
            }
        }
        __syncthreads();
    }

    float inv0 = 1.f / l0, inv1 = 1.f / l1;
    int row0 = q0 + wid * 16 + gr;
    size_t base0 = ((size_t)b * NW + row0) * DM + h * DK;
    #pragma unroll
    for (int j = 0; j < 8; j++) {
        int d = 8 * j + 2 * c;
        *(__half2*)(g_ao + base0 + d) =
            __floats2half2_rn(oacc[j][0] * inv0, oacc[j][1] * inv0);
        *(__half2*)(g_ao + base0 + 8 * DM + d) =
            __floats2half2_rn(oacc[j][2] * inv1, oacc[j][3] * inv1);
    }
}

// ============================================================
extern "C" void kernel_launch(void* const* d_in, const int* in_sizes, int n_in,
                              void* d_out, int out_size) {
    const float* Q  = (const float*)d_in[0];
    const float* K  = (const float*)d_in[1];
    const float* V  = (const float*)d_in[2];
    const int* mask = (const int*)d_in[3];
    const float* Wq = (const float*)d_in[4];
    const float* Wk = (const float*)d_in[5];
    const float* Wv = (const float*)d_in[6];
    const float* Wo = (const float*)d_in[7];
    float* out = (float*)d_out;

    static int attr_done = 0;
    if (!attr_done) {
        cudaFuncSetAttribute(proj_mma_kernel, cudaFuncAttributeMaxDynamicSharedMemorySize, SMEM_MMA);
        cudaFuncSetAttribute(out_mma_kernel, cudaFuncAttributeMaxDynamicSharedMemorySize, SMEM_MMA);
        cudaFuncSetAttribute(flash_mma_kernel, cudaFuncAttributeMaxDynamicSharedMemorySize, SMEM_FLASH);
        attr_done = 1;
    }

    prep_kernel<<<PREP_BLKS, 256>>>(mask, Q, K, V, Wq, Wk, Wv, Wo);
    proj_mma_kernel<<<dim3(DM / 128, MT / 128, 3), 256, SMEM_MMA>>>();
    flash_mma_kernel<<<dim3(NW / 128, NH, NB), 256, SMEM_FLASH>>>();
    out_mma_kernel<<<dim3(DM / 128, MT / 128), 256, SMEM_MMA>>>(out);
}